// round 8
// baseline (speedup 1.0000x reference)
#include <cuda_runtime.h>
#include <cuda_bf16.h>
#include <cstdint>

// Problem constants (fixed shapes)
#define B_   8
#define S_   4096
#define H_   768      // K of GEMM
#define D_   1024     // N of GEMM
#define W_   2048     // MAX_WORDS
#define M_   (B_ * W_)   // 16384 GEMM rows

// ---------------------------------------------------------------------------
// Device scratch (no allocations allowed anywhere)
// ---------------------------------------------------------------------------
__device__ __nv_bfloat16 g_a_hi[(size_t)M_ * H_];   // pooled rows, hi plane
__device__ __nv_bfloat16 g_a_lo[(size_t)M_ * H_];   // pooled rows, lo plane
__device__ __nv_bfloat16 g_bt_hi[(size_t)D_ * H_];  // proj_w^T [N][K] hi
__device__ __nv_bfloat16 g_bt_lo[(size_t)D_ * H_];  // proj_w^T [N][K] lo

// ---------------------------------------------------------------------------
// Kernel 1: per-(b,w) segment masked-mean pooling, float4-vectorized.
// ---------------------------------------------------------------------------
__global__ void __launch_bounds__(192)
seg_mean_kernel(const float* __restrict__ emb,      // [B,S,H]
                const int*   __restrict__ masks,    // [B,S]
                const int*   __restrict__ wids,     // [B,S] sorted per b
                float*       __restrict__ mask_out) // [M_]
{
    const int w = blockIdx.x;   // word id  [0, W_)
    const int b = blockIdx.y;   // batch    [0, B_)
    const int* row = wids + (size_t)b * S_;

    // lower bound: first s with row[s] >= w
    int lo = 0, hi = S_;
    while (lo < hi) { int m = (lo + hi) >> 1; if (row[m] < w) lo = m + 1; else hi = m; }
    const int start = lo;
    // upper bound: first s with row[s] > w
    hi = S_;
    while (lo < hi) { int m = (lo + hi) >> 1; if (row[m] <= w) lo = m + 1; else hi = m; }
    const int end = lo;
    const int count = end - start;

    __shared__ int s_ok;
    if (threadIdx.x == 0) s_ok = 1;
    __syncthreads();
    const int* mrow = masks + (size_t)b * S_;
    for (int s = start + threadIdx.x; s < end; s += 192)
        if (mrow[s] == 0) s_ok = 0;   // benign race: all writers write 0
    __syncthreads();

    const bool valid = (count > 0) && (s_ok != 0);
    const float inv = valid ? (1.0f / (float)count) : 0.0f;

    const float4* ebase4 = (const float4*)(emb + ((size_t)b * S_ + start) * H_);
    const int idx = b * W_ + w;
    __nv_bfloat16* ohi = g_a_hi + (size_t)idx * H_;
    __nv_bfloat16* olo = g_a_lo + (size_t)idx * H_;

    // H_/4 = 192 float4 per row; one per thread.
    {
        const int h4 = threadIdx.x;
        float4 acc = make_float4(0.f, 0.f, 0.f, 0.f);
        for (int s = 0; s < count; ++s) {
            float4 v = ebase4[(size_t)s * (H_ / 4) + h4];
            acc.x += v.x; acc.y += v.y; acc.z += v.z; acc.w += v.w;
        }
        float vx = acc.x * inv, vy = acc.y * inv, vz = acc.z * inv, vw = acc.w * inv;
        __nv_bfloat162 h01 = __floats2bfloat162_rn(vx, vy);
        __nv_bfloat162 h23 = __floats2bfloat162_rn(vz, vw);
        __nv_bfloat162 l01 = __floats2bfloat162_rn(vx - __bfloat162float(h01.x),
                                                   vy - __bfloat162float(h01.y));
        __nv_bfloat162 l23 = __floats2bfloat162_rn(vz - __bfloat162float(h23.x),
                                                   vw - __bfloat162float(h23.y));
        uint2 uh, ul;
        uh.x = *(uint32_t*)&h01; uh.y = *(uint32_t*)&h23;
        ul.x = *(uint32_t*)&l01; ul.y = *(uint32_t*)&l23;
        *(uint2*)&ohi[h4 * 4] = uh;
        *(uint2*)&olo[h4 * 4] = ul;
    }
    if (threadIdx.x == 0)
        mask_out[idx] = valid ? 1.0f : 0.0f;
}

// ---------------------------------------------------------------------------
// Kernel 2: proj_w [K=768][N=1024] -> transposed bf16 hi/lo planes [N][K]
// ---------------------------------------------------------------------------
__global__ void __launch_bounds__(256)
wsplit_kernel(const float* __restrict__ w)
{
    __shared__ float t[32][33];
    const int nx = blockIdx.x * 32, kx = blockIdx.y * 32;
    const int tx = threadIdx.x, ty = threadIdx.y;   // 32 x 8
    #pragma unroll
    for (int j = 0; j < 32; j += 8)
        t[ty + j][tx] = w[(size_t)(kx + ty + j) * D_ + nx + tx];
    __syncthreads();
    #pragma unroll
    for (int j = 0; j < 32; j += 8) {
        int n = nx + ty + j, k = kx + tx;
        float v = t[tx][ty + j];
        __nv_bfloat16 vh = __float2bfloat16(v);
        g_bt_hi[(size_t)n * H_ + k] = vh;
        g_bt_lo[(size_t)n * H_ + k] = __float2bfloat16(v - __bfloat162float(vh));
    }
}

// ---------------------------------------------------------------------------
// mma.sync / ldmatrix / cp.async helpers (sm_80+, legal on both passes)
// ---------------------------------------------------------------------------
__device__ __forceinline__ void ldsm_x4(uint32_t* r, uint32_t addr) {
    asm volatile("ldmatrix.sync.aligned.m8n8.x4.shared.b16 {%0,%1,%2,%3}, [%4];"
                 : "=r"(r[0]), "=r"(r[1]), "=r"(r[2]), "=r"(r[3]) : "r"(addr));
}
__device__ __forceinline__ void mma_bf16(float* d, const uint32_t* a, const uint32_t* b) {
    asm volatile(
        "mma.sync.aligned.m16n8k16.row.col.f32.bf16.bf16.f32 "
        "{%0,%1,%2,%3}, {%4,%5,%6,%7}, {%8,%9}, {%0,%1,%2,%3};"
        : "+f"(d[0]), "+f"(d[1]), "+f"(d[2]), "+f"(d[3])
        : "r"(a[0]), "r"(a[1]), "r"(a[2]), "r"(a[3]), "r"(b[0]), "r"(b[1]));
}
__device__ __forceinline__ void cp16(uint32_t dst, const void* src) {
    asm volatile("cp.async.cg.shared.global [%0], [%1], 16;" :: "r"(dst), "l"(src));
}
__device__ __forceinline__ void cp_commit() {
    asm volatile("cp.async.commit_group;" ::: "memory");
}
template <int N> __device__ __forceinline__ void cp_wait() {
    asm volatile("cp.async.wait_group %0;" :: "n"(N) : "memory");
}

// ---------------------------------------------------------------------------
// Kernel 3: GEMM via mma.sync bf16, 3-product split, fp32 accum,
// cp.async double-buffered. C[M,N] = Ahi*Bhi + Ahi*Blo + Alo*Bhi + bias.
// Block tile 128x128, BK=32; 8 warps, warp tile 64x32.
// smem pitch 40 bf16 (80B) -> ldmatrix conflict-free.
// ---------------------------------------------------------------------------
#define BK 32
#define NCH (H_ / BK)            // 24
#define PITCH 40                 // bf16 per smem row
#define PLANE_B (128 * PITCH * 2)   // 10240 bytes
#define STAGE_B (4 * PLANE_B)       // 40960 bytes
#define GEMM_SMEM (2 * STAGE_B)     // 81920 bytes

__global__ void __launch_bounds__(256, 2)
gemm_mma_kernel(const float* __restrict__ bias, float* __restrict__ C)
{
    extern __shared__ __align__(16) char sm[];
    const uint32_t sm_b = (uint32_t)__cvta_generic_to_shared(sm);

    const int tid  = threadIdx.x;
    const int wid  = tid >> 5;
    const int lane = tid & 31;
    const int m0 = blockIdx.y * 128;
    const int n0 = blockIdx.x * 128;
    const int wm = (wid & 1) * 64;     // warp M origin within tile
    const int wn = (wid >> 1) * 32;    // warp N origin within tile

    // ldmatrix lane coords (within 16x16 block):
    const int matq = lane >> 3;
    const int lrow = lane & 7;
    const int a_r = lrow + ((matq & 1) << 3);
    const int a_c = (matq >> 1) << 3;
    const int b_r = lrow + ((matq >> 1) << 3);
    const int b_c = (matq & 1) << 3;

    float acc[4][4][4];
    #pragma unroll
    for (int i = 0; i < 4; ++i)
        #pragma unroll
        for (int j = 0; j < 4; ++j)
            #pragma unroll
            for (int k = 0; k < 4; ++k) acc[i][j][k] = 0.0f;

    // cp.async stage loader: 4 planes x 128 rows x 64B (4x16B chunks per row)
    auto load_stage = [&](int stage, int k0) {
        const uint32_t st = sm_b + stage * STAGE_B;
        #pragma unroll
        for (int i = tid; i < 512; i += 256) {      // plane 0: A hi
            const int r = i >> 2, c = (i & 3) << 3;
            cp16(st + (uint32_t)(r * PITCH + c) * 2,
                 g_a_hi + (size_t)(m0 + r) * H_ + k0 + c);
        }
        #pragma unroll
        for (int i = tid; i < 512; i += 256) {      // plane 1: A lo
            const int r = i >> 2, c = (i & 3) << 3;
            cp16(st + PLANE_B + (uint32_t)(r * PITCH + c) * 2,
                 g_a_lo + (size_t)(m0 + r) * H_ + k0 + c);
        }
        #pragma unroll
        for (int i = tid; i < 512; i += 256) {      // plane 2: B hi
            const int r = i >> 2, c = (i & 3) << 3;
            cp16(st + 2 * PLANE_B + (uint32_t)(r * PITCH + c) * 2,
                 g_bt_hi + (size_t)(n0 + r) * H_ + k0 + c);
        }
        #pragma unroll
        for (int i = tid; i < 512; i += 256) {      // plane 3: B lo
            const int r = i >> 2, c = (i & 3) << 3;
            cp16(st + 3 * PLANE_B + (uint32_t)(r * PITCH + c) * 2,
                 g_bt_lo + (size_t)(n0 + r) * H_ + k0 + c);
        }
        cp_commit();
    };

    load_stage(0, 0);

    for (int c = 0; c < NCH; ++c) {
        if (c + 1 < NCH) load_stage((c + 1) & 1, (c + 1) * BK);
        if (c + 1 < NCH) cp_wait<1>(); else cp_wait<0>();
        __syncthreads();

        const uint32_t st = sm_b + (c & 1) * STAGE_B;
        const uint32_t sAh_b = st;
        const uint32_t sAl_b = st + PLANE_B;
        const uint32_t sBh_b = st + 2 * PLANE_B;
        const uint32_t sBl_b = st + 3 * PLANE_B;

        #pragma unroll
        for (int ks = 0; ks < 2; ++ks) {
            const int ko = ks * 16;
            uint32_t ah[4][4], bh[4][2], bl[4][2];
            #pragma unroll
            for (int mf = 0; mf < 4; ++mf) {
                const int r = wm + mf * 16 + a_r;
                ldsm_x4(ah[mf], sAh_b + (uint32_t)(r * PITCH + ko + a_c) * 2);
            }
            #pragma unroll
            for (int np = 0; np < 2; ++np) {
                const int r = wn + np * 16 + b_r;
                const uint32_t off = (uint32_t)(r * PITCH + ko + b_c) * 2;
                uint32_t q[4];
                ldsm_x4(q, sBh_b + off);
                bh[np * 2][0] = q[0]; bh[np * 2][1] = q[1];
                bh[np * 2 + 1][0] = q[2]; bh[np * 2 + 1][1] = q[3];
                ldsm_x4(q, sBl_b + off);
                bl[np * 2][0] = q[0]; bl[np * 2][1] = q[1];
                bl[np * 2 + 1][0] = q[2]; bl[np * 2 + 1][1] = q[3];
            }
            #pragma unroll
            for (int mf = 0; mf < 4; ++mf)
                #pragma unroll
                for (int nf = 0; nf < 4; ++nf) {
                    mma_bf16(acc[mf][nf], ah[mf], bh[nf]);
                    mma_bf16(acc[mf][nf], ah[mf], bl[nf]);
                }
            uint32_t al[4][4];
            #pragma unroll
            for (int mf = 0; mf < 4; ++mf) {
                const int r = wm + mf * 16 + a_r;
                ldsm_x4(al[mf], sAl_b + (uint32_t)(r * PITCH + ko + a_c) * 2);
            }
            #pragma unroll
            for (int mf = 0; mf < 4; ++mf)
                #pragma unroll
                for (int nf = 0; nf < 4; ++nf)
                    mma_bf16(acc[mf][nf], al[mf], bh[nf]);
        }
        __syncthreads();   // stage consumed; safe for the load 2 iterations ahead
    }

    // Epilogue: direct gmem stores with bias.
    const int cr = lane >> 2;
    const int cc = (lane & 3) * 2;
    #pragma unroll
    for (int mf = 0; mf < 4; ++mf) {
        #pragma unroll
        for (int nf = 0; nf < 4; ++nf) {
            const int gr0 = m0 + wm + mf * 16 + cr;
            const int gc  = n0 + wn + nf * 8 + cc;
            const float b0 = bias[gc], b1 = bias[gc + 1];
            float2 v0 = make_float2(acc[mf][nf][0] + b0, acc[mf][nf][1] + b1);
            float2 v1 = make_float2(acc[mf][nf][2] + b0, acc[mf][nf][3] + b1);
            *(float2*)&C[(size_t)gr0 * D_ + gc]       = v0;
            *(float2*)&C[(size_t)(gr0 + 8) * D_ + gc] = v1;
        }
    }
}

// ---------------------------------------------------------------------------
// Launch. d_out: [ out (M_*D_ f32) | token_masks (M_ f32 0/1) ]
// ---------------------------------------------------------------------------
extern "C" void kernel_launch(void* const* d_in, const int* in_sizes, int n_in,
                              void* d_out, int out_size)
{
    const float* emb    = (const float*)d_in[0];
    const float* proj_w = (const float*)d_in[1];
    const float* proj_b = (const float*)d_in[2];
    const int*   masks  = (const int*)d_in[3];
    const int*   wids   = (const int*)d_in[4];

    float* out_proj  = (float*)d_out;
    float* out_masks = (float*)d_out + (size_t)M_ * D_;

    cudaFuncSetAttribute(gemm_mma_kernel,
                         cudaFuncAttributeMaxDynamicSharedMemorySize, GEMM_SMEM);

    dim3 g1(W_, B_);
    seg_mean_kernel<<<g1, 192>>>(emb, masks, wids, out_masks);

    dim3 gw(D_ / 32, H_ / 32);
    wsplit_kernel<<<gw, dim3(32, 8)>>>(proj_w);

    dim3 g2(D_ / 128, M_ / 128);   // (8, 128)
    gemm_mma_kernel<<<g2, 256, GEMM_SMEM>>>(proj_b, out_proj);
}

// round 10
// speedup vs baseline: 1.6288x; 1.6288x over previous
#include <cuda_runtime.h>
#include <cuda_bf16.h>
#include <cstdint>

// Problem constants (fixed shapes)
#define B_   8
#define S_   4096
#define H_   768      // K of GEMM
#define D_   1024     // N of GEMM
#define W_   2048     // MAX_WORDS
#define M_   (B_ * W_)   // 16384 GEMM rows

// ---------------------------------------------------------------------------
// Device scratch (no allocations allowed anywhere)
// ---------------------------------------------------------------------------
__device__ __nv_bfloat16 g_a_hi[(size_t)M_ * H_];   // pooled rows, hi plane
__device__ __nv_bfloat16 g_a_lo[(size_t)M_ * H_];   // pooled rows, lo plane
__device__ __nv_bfloat16 g_bt_hi[(size_t)D_ * H_];  // proj_w^T [N][K] hi
__device__ __nv_bfloat16 g_bt_lo[(size_t)D_ * H_];  // proj_w^T [N][K] lo
__device__ int g_wstart[M_];
__device__ int g_wend[M_];

// ---------------------------------------------------------------------------
// Boundary pre-pass: word_ids sorted per batch -> contiguous runs.
// One coalesced sweep replaces per-word binary searches.
// ---------------------------------------------------------------------------
__global__ void __launch_bounds__(256) zero_bounds_kernel() {
    int i = blockIdx.x * 256 + threadIdx.x;
    if (i < M_) { g_wstart[i] = 0; g_wend[i] = 0; }
}
__global__ void __launch_bounds__(256) calc_bounds_kernel(const int* __restrict__ wids) {
    int i = blockIdx.x * 256 + threadIdx.x;     // over B_*S_
    int b = i >> 12;                            // S_ = 4096
    int s = i & (S_ - 1);
    int w = wids[i];
    if (s == 0      || wids[i - 1] != w) g_wstart[b * W_ + w] = s;
    if (s == S_ - 1 || wids[i + 1] != w) g_wend[b * W_ + w] = s + 1;
}

// ---------------------------------------------------------------------------
// Kernel 1: per-(b,w) segment masked-mean pooling, float4-vectorized,
// bounds read directly (no binary search).
// ---------------------------------------------------------------------------
__global__ void __launch_bounds__(192)
seg_mean_kernel(const float* __restrict__ emb,      // [B,S,H]
                const int*   __restrict__ masks,    // [B,S]
                float*       __restrict__ mask_out) // [M_]
{
    const int w = blockIdx.x;   // word id  [0, W_)
    const int b = blockIdx.y;   // batch    [0, B_)
    const int idx = b * W_ + w;
    const int start = g_wstart[idx];
    const int end   = g_wend[idx];
    const int count = end - start;

    __shared__ int s_ok;
    if (threadIdx.x == 0) s_ok = 1;
    __syncthreads();
    const int* mrow = masks + (size_t)b * S_;
    for (int s = start + threadIdx.x; s < end; s += 192)
        if (mrow[s] == 0) s_ok = 0;   // benign race: all writers write 0
    __syncthreads();

    const bool valid = (count > 0) && (s_ok != 0);
    const float inv = valid ? (1.0f / (float)count) : 0.0f;

    const float4* ebase4 = (const float4*)(emb + ((size_t)b * S_ + start) * H_);
    __nv_bfloat16* ohi = g_a_hi + (size_t)idx * H_;
    __nv_bfloat16* olo = g_a_lo + (size_t)idx * H_;

    // H_/4 = 192 float4 per row; one per thread.
    {
        const int h4 = threadIdx.x;
        float4 acc = make_float4(0.f, 0.f, 0.f, 0.f);
        for (int s = 0; s < count; ++s) {
            float4 v = ebase4[(size_t)s * (H_ / 4) + h4];
            acc.x += v.x; acc.y += v.y; acc.z += v.z; acc.w += v.w;
        }
        float vx = acc.x * inv, vy = acc.y * inv, vz = acc.z * inv, vw = acc.w * inv;
        __nv_bfloat162 h01 = __floats2bfloat162_rn(vx, vy);
        __nv_bfloat162 h23 = __floats2bfloat162_rn(vz, vw);
        __nv_bfloat162 l01 = __floats2bfloat162_rn(vx - __bfloat162float(h01.x),
                                                   vy - __bfloat162float(h01.y));
        __nv_bfloat162 l23 = __floats2bfloat162_rn(vz - __bfloat162float(h23.x),
                                                   vw - __bfloat162float(h23.y));
        uint2 uh, ul;
        uh.x = *(uint32_t*)&h01; uh.y = *(uint32_t*)&h23;
        ul.x = *(uint32_t*)&l01; ul.y = *(uint32_t*)&l23;
        *(uint2*)&ohi[h4 * 4] = uh;
        *(uint2*)&olo[h4 * 4] = ul;
    }
    if (threadIdx.x == 0)
        mask_out[idx] = valid ? 1.0f : 0.0f;
}

// ---------------------------------------------------------------------------
// Kernel 2: proj_w [K=768][N=1024] -> transposed bf16 hi/lo planes [N][K]
// ---------------------------------------------------------------------------
__global__ void __launch_bounds__(256)
wsplit_kernel(const float* __restrict__ w)
{
    __shared__ float t[32][33];
    const int nx = blockIdx.x * 32, kx = blockIdx.y * 32;
    const int tx = threadIdx.x, ty = threadIdx.y;   // 32 x 8
    #pragma unroll
    for (int j = 0; j < 32; j += 8)
        t[ty + j][tx] = w[(size_t)(kx + ty + j) * D_ + nx + tx];
    __syncthreads();
    #pragma unroll
    for (int j = 0; j < 32; j += 8) {
        int n = nx + ty + j, k = kx + tx;
        float v = t[tx][ty + j];
        __nv_bfloat16 vh = __float2bfloat16(v);
        g_bt_hi[(size_t)n * H_ + k] = vh;
        g_bt_lo[(size_t)n * H_ + k] = __float2bfloat16(v - __bfloat162float(vh));
    }
}

// ---------------------------------------------------------------------------
// mma.sync / ldmatrix helpers (sm_80+ -- legal on BOTH device compile passes)
// ---------------------------------------------------------------------------
__device__ __forceinline__ void ldsm_x4(uint32_t* r, uint32_t addr) {
    asm volatile("ldmatrix.sync.aligned.m8n8.x4.shared.b16 {%0,%1,%2,%3}, [%4];"
                 : "=r"(r[0]), "=r"(r[1]), "=r"(r[2]), "=r"(r[3]) : "r"(addr));
}
__device__ __forceinline__ void mma_bf16(float* d, const uint32_t* a, const uint32_t* b) {
    asm volatile(
        "mma.sync.aligned.m16n8k16.row.col.f32.bf16.bf16.f32 "
        "{%0,%1,%2,%3}, {%4,%5,%6,%7}, {%8,%9}, {%0,%1,%2,%3};"
        : "+f"(d[0]), "+f"(d[1]), "+f"(d[2]), "+f"(d[3])
        : "r"(a[0]), "r"(a[1]), "r"(a[2]), "r"(a[3]), "r"(b[0]), "r"(b[1]));
}

// ---------------------------------------------------------------------------
// Kernel 3: GEMM via mma.sync bf16 (EXACT R7 version -- proven 223us).
//   C[M,N] = Ahi*Bhi + Ahi*Blo + Alo*Bhi + bias
// Block tile 128x128, BK=32; 8 warps, warp tile 64x32.
// smem pitch 40 bf16 (80B) -> ldmatrix conflict-free.
// ---------------------------------------------------------------------------
#define BK 32
#define PITCH 40   // bf16 elements per smem row

__global__ void __launch_bounds__(256, 2)
gemm_mma_kernel(const float* __restrict__ bias, float* __restrict__ C)
{
    __shared__ __align__(16) __nv_bfloat16 sAh[128 * PITCH];
    __shared__ __align__(16) __nv_bfloat16 sAl[128 * PITCH];
    __shared__ __align__(16) __nv_bfloat16 sBh[128 * PITCH];
    __shared__ __align__(16) __nv_bfloat16 sBl[128 * PITCH];

    const int tid  = threadIdx.x;
    const int wid  = tid >> 5;
    const int lane = tid & 31;
    const int m0 = blockIdx.y * 128;
    const int n0 = blockIdx.x * 128;
    const int wm = (wid & 1) * 64;     // warp M origin within tile
    const int wn = (wid >> 1) * 32;    // warp N origin within tile

    const uint32_t sAh_b = (uint32_t)__cvta_generic_to_shared(sAh);
    const uint32_t sAl_b = (uint32_t)__cvta_generic_to_shared(sAl);
    const uint32_t sBh_b = (uint32_t)__cvta_generic_to_shared(sBh);
    const uint32_t sBl_b = (uint32_t)__cvta_generic_to_shared(sBl);

    // ldmatrix lane coords (within 16x16 block):
    const int matq = lane >> 3;
    const int lrow = lane & 7;
    const int a_r = lrow + ((matq & 1) << 3);
    const int a_c = (matq >> 1) << 3;
    const int b_r = lrow + ((matq >> 1) << 3);
    const int b_c = (matq & 1) << 3;

    float acc[4][4][4];
    #pragma unroll
    for (int i = 0; i < 4; ++i)
        #pragma unroll
        for (int j = 0; j < 4; ++j)
            #pragma unroll
            for (int k = 0; k < 4; ++k) acc[i][j][k] = 0.0f;

    for (int k0 = 0; k0 < H_; k0 += BK) {
        __syncthreads();   // previous iteration's math done before overwrite
        #pragma unroll
        for (int i = tid; i < 512; i += 256) {
            const int r = i >> 2;
            const int c = (i & 3) << 3;     // bf16 col, 8 per uint4
            const size_t ga = (size_t)(m0 + r) * H_ + k0 + c;
            const size_t gb = (size_t)(n0 + r) * H_ + k0 + c;
            *(uint4*)&sAh[r * PITCH + c] = *(const uint4*)&g_a_hi[ga];
            *(uint4*)&sAl[r * PITCH + c] = *(const uint4*)&g_a_lo[ga];
            *(uint4*)&sBh[r * PITCH + c] = *(const uint4*)&g_bt_hi[gb];
            *(uint4*)&sBl[r * PITCH + c] = *(const uint4*)&g_bt_lo[gb];
        }
        __syncthreads();

        #pragma unroll
        for (int ks = 0; ks < 2; ++ks) {
            const int ko = ks * 16;
            uint32_t ah[4][4], bh[4][2], bl[4][2];
            #pragma unroll
            for (int mf = 0; mf < 4; ++mf) {
                const int r = wm + mf * 16 + a_r;
                ldsm_x4(ah[mf], sAh_b + (uint32_t)(r * PITCH + ko + a_c) * 2);
            }
            #pragma unroll
            for (int np = 0; np < 2; ++np) {
                const int r = wn + np * 16 + b_r;
                const uint32_t off = (uint32_t)(r * PITCH + ko + b_c) * 2;
                uint32_t q[4];
                ldsm_x4(q, sBh_b + off);
                bh[np * 2][0] = q[0]; bh[np * 2][1] = q[1];
                bh[np * 2 + 1][0] = q[2]; bh[np * 2 + 1][1] = q[3];
                ldsm_x4(q, sBl_b + off);
                bl[np * 2][0] = q[0]; bl[np * 2][1] = q[1];
                bl[np * 2 + 1][0] = q[2]; bl[np * 2 + 1][1] = q[3];
            }
            #pragma unroll
            for (int mf = 0; mf < 4; ++mf)
                #pragma unroll
                for (int nf = 0; nf < 4; ++nf) {
                    mma_bf16(acc[mf][nf], ah[mf], bh[nf]);
                    mma_bf16(acc[mf][nf], ah[mf], bl[nf]);
                }
            uint32_t al[4][4];
            #pragma unroll
            for (int mf = 0; mf < 4; ++mf) {
                const int r = wm + mf * 16 + a_r;
                ldsm_x4(al[mf], sAl_b + (uint32_t)(r * PITCH + ko + a_c) * 2);
            }
            #pragma unroll
            for (int mf = 0; mf < 4; ++mf)
                #pragma unroll
                for (int nf = 0; nf < 4; ++nf)
                    mma_bf16(acc[mf][nf], al[mf], bh[nf]);
        }
    }

    // Epilogue: direct gmem stores with bias.
    const int cr = lane >> 2;
    const int cc = (lane & 3) * 2;
    #pragma unroll
    for (int mf = 0; mf < 4; ++mf) {
        #pragma unroll
        for (int nf = 0; nf < 4; ++nf) {
            const int gr0 = m0 + wm + mf * 16 + cr;
            const int gc  = n0 + wn + nf * 8 + cc;
            const float b0 = bias[gc], b1 = bias[gc + 1];
            float2 v0 = make_float2(acc[mf][nf][0] + b0, acc[mf][nf][1] + b1);
            float2 v1 = make_float2(acc[mf][nf][2] + b0, acc[mf][nf][3] + b1);
            *(float2*)&C[(size_t)gr0 * D_ + gc]       = v0;
            *(float2*)&C[(size_t)(gr0 + 8) * D_ + gc] = v1;
        }
    }
}

// ---------------------------------------------------------------------------
// Launch. Inputs (metadata order):
//   d_in[0] embeddings f32 [B,S,H]; d_in[1] proj_w f32 [H,D]; d_in[2] proj_b f32 [D]
//   d_in[3] masks i32 [B,S]; d_in[4] word_ids i32 [B,S]
// d_out: [ out (M_*D_ f32) | token_masks (M_ f32 0/1) ]
// ---------------------------------------------------------------------------
extern "C" void kernel_launch(void* const* d_in, const int* in_sizes, int n_in,
                              void* d_out, int out_size)
{
    const float* emb    = (const float*)d_in[0];
    const float* proj_w = (const float*)d_in[1];
    const float* proj_b = (const float*)d_in[2];
    const int*   masks  = (const int*)d_in[3];
    const int*   wids   = (const int*)d_in[4];

    float* out_proj  = (float*)d_out;
    float* out_masks = (float*)d_out + (size_t)M_ * D_;

    zero_bounds_kernel<<<M_ / 256, 256>>>();
    calc_bounds_kernel<<<(B_ * S_) / 256, 256>>>(wids);

    dim3 g1(W_, B_);
    seg_mean_kernel<<<g1, 192>>>(emb, masks, out_masks);

    dim3 gw(D_ / 32, H_ / 32);
    wsplit_kernel<<<gw, dim3(32, 8)>>>(proj_w);

    dim3 g2(D_ / 128, M_ / 128);   // (8, 128)
    gemm_mma_kernel<<<g2, 256>>>(proj_b, out_proj);
}

// round 12
// speedup vs baseline: 1.8646x; 1.1448x over previous
#include <cuda_runtime.h>
#include <cuda_fp16.h>
#include <cstdint>

// Problem constants (fixed shapes)
#define B_   8
#define S_   4096
#define H_   768      // K of GEMM
#define D_   1024     // N of GEMM
#define W_   2048     // MAX_WORDS
#define M_   (B_ * W_)   // 16384 GEMM rows

// ---------------------------------------------------------------------------
// Device scratch (no allocations allowed anywhere)
// ---------------------------------------------------------------------------
__device__ __half g_a_hi[(size_t)M_ * H_];   // pooled rows, fp16 hi plane
__device__ __half g_a_lo[(size_t)M_ * H_];   // pooled rows, fp16 lo plane (x - hi)
__device__ __half g_bt[(size_t)D_ * H_];     // proj_w^T [N][K] single fp16 plane
__device__ int g_wstart[M_];
__device__ int g_wend[M_];

// ---------------------------------------------------------------------------
// Boundary pre-pass: word_ids sorted per batch -> contiguous runs.
// ---------------------------------------------------------------------------
__global__ void __launch_bounds__(256) zero_bounds_kernel() {
    int i = blockIdx.x * 256 + threadIdx.x;
    if (i < M_) { g_wstart[i] = 0; g_wend[i] = 0; }
}
__global__ void __launch_bounds__(256) calc_bounds_kernel(const int* __restrict__ wids) {
    int i = blockIdx.x * 256 + threadIdx.x;     // over B_*S_
    int b = i >> 12;                            // S_ = 4096
    int s = i & (S_ - 1);
    int w = wids[i];
    if (s == 0      || wids[i - 1] != w) g_wstart[b * W_ + w] = s;
    if (s == S_ - 1 || wids[i + 1] != w) g_wend[b * W_ + w] = s + 1;
}

// ---------------------------------------------------------------------------
// Kernel 1: per-(b,w) segment masked-mean pooling -> fp16 hi/lo planes.
// ---------------------------------------------------------------------------
__global__ void __launch_bounds__(192)
seg_mean_kernel(const float* __restrict__ emb,      // [B,S,H]
                const int*   __restrict__ masks,    // [B,S]
                float*       __restrict__ mask_out) // [M_]
{
    const int w = blockIdx.x;   // word id  [0, W_)
    const int b = blockIdx.y;   // batch    [0, B_)
    const int idx = b * W_ + w;
    const int start = g_wstart[idx];
    const int end   = g_wend[idx];
    const int count = end - start;

    __shared__ int s_ok;
    if (threadIdx.x == 0) s_ok = 1;
    __syncthreads();
    const int* mrow = masks + (size_t)b * S_;
    for (int s = start + threadIdx.x; s < end; s += 192)
        if (mrow[s] == 0) s_ok = 0;   // benign race: all writers write 0
    __syncthreads();

    const bool valid = (count > 0) && (s_ok != 0);
    const float inv = valid ? (1.0f / (float)count) : 0.0f;

    const float4* ebase4 = (const float4*)(emb + ((size_t)b * S_ + start) * H_);
    __half* ohi = g_a_hi + (size_t)idx * H_;
    __half* olo = g_a_lo + (size_t)idx * H_;

    // H_/4 = 192 float4 per row; one per thread.
    {
        const int h4 = threadIdx.x;
        float4 acc = make_float4(0.f, 0.f, 0.f, 0.f);
        for (int s = 0; s < count; ++s) {
            float4 v = ebase4[(size_t)s * (H_ / 4) + h4];
            acc.x += v.x; acc.y += v.y; acc.z += v.z; acc.w += v.w;
        }
        float vx = acc.x * inv, vy = acc.y * inv, vz = acc.z * inv, vw = acc.w * inv;
        __half2 h01 = __floats2half2_rn(vx, vy);
        __half2 h23 = __floats2half2_rn(vz, vw);
        __half2 l01 = __floats2half2_rn(vx - __half2float(h01.x),
                                        vy - __half2float(h01.y));
        __half2 l23 = __floats2half2_rn(vz - __half2float(h23.x),
                                        vw - __half2float(h23.y));
        uint2 uh, ul;
        uh.x = *(uint32_t*)&h01; uh.y = *(uint32_t*)&h23;
        ul.x = *(uint32_t*)&l01; ul.y = *(uint32_t*)&l23;
        *(uint2*)&ohi[h4 * 4] = uh;
        *(uint2*)&olo[h4 * 4] = ul;
    }
    if (threadIdx.x == 0)
        mask_out[idx] = valid ? 1.0f : 0.0f;
}

// ---------------------------------------------------------------------------
// Kernel 2: proj_w [K=768][N=1024] -> transposed single fp16 plane [N][K]
// ---------------------------------------------------------------------------
__global__ void __launch_bounds__(256)
wsplit_kernel(const float* __restrict__ w)
{
    __shared__ float t[32][33];
    const int nx = blockIdx.x * 32, kx = blockIdx.y * 32;
    const int tx = threadIdx.x, ty = threadIdx.y;   // 32 x 8
    #pragma unroll
    for (int j = 0; j < 32; j += 8)
        t[ty + j][tx] = w[(size_t)(kx + ty + j) * D_ + nx + tx];
    __syncthreads();
    #pragma unroll
    for (int j = 0; j < 32; j += 8) {
        int n = nx + ty + j, k = kx + tx;
        g_bt[(size_t)n * H_ + k] = __float2half_rn(t[tx][ty + j]);
    }
}

// ---------------------------------------------------------------------------
// mma.sync / ldmatrix helpers (sm_80+ -- legal on BOTH device compile passes)
// ---------------------------------------------------------------------------
__device__ __forceinline__ void ldsm_x4(uint32_t* r, uint32_t addr) {
    asm volatile("ldmatrix.sync.aligned.m8n8.x4.shared.b16 {%0,%1,%2,%3}, [%4];"
                 : "=r"(r[0]), "=r"(r[1]), "=r"(r[2]), "=r"(r[3]) : "r"(addr));
}
__device__ __forceinline__ void mma_f16(float* d, const uint32_t* a, const uint32_t* b) {
    asm volatile(
        "mma.sync.aligned.m16n8k16.row.col.f32.f16.f16.f32 "
        "{%0,%1,%2,%3}, {%4,%5,%6,%7}, {%8,%9}, {%0,%1,%2,%3};"
        : "+f"(d[0]), "+f"(d[1]), "+f"(d[2]), "+f"(d[3])
        : "r"(a[0]), "r"(a[1]), "r"(a[2]), "r"(a[3]), "r"(b[0]), "r"(b[1]));
}

// ---------------------------------------------------------------------------
// Kernel 3: GEMM via mma.sync fp16, 2-product split, fp32 accum.
//   C[M,N] = Ahi*B + Alo*B + bias       (B single fp16 plane)
// Structure identical to the proven R7 kernel; one fewer operand plane.
// Block tile 128x128, BK=32; 8 warps, warp tile 64x32.
// smem pitch 40 halves (80B) -> ldmatrix conflict-free.
// ---------------------------------------------------------------------------
#define BK 32
#define PITCH 40   // fp16 elements per smem row

__global__ void __launch_bounds__(256, 2)
gemm_mma_kernel(const float* __restrict__ bias, float* __restrict__ C)
{
    __shared__ __align__(16) __half sAh[128 * PITCH];
    __shared__ __align__(16) __half sAl[128 * PITCH];
    __shared__ __align__(16) __half sB [128 * PITCH];

    const int tid  = threadIdx.x;
    const int wid  = tid >> 5;
    const int lane = tid & 31;
    const int m0 = blockIdx.y * 128;
    const int n0 = blockIdx.x * 128;
    const int wm = (wid & 1) * 64;     // warp M origin within tile
    const int wn = (wid >> 1) * 32;    // warp N origin within tile

    const uint32_t sAh_b = (uint32_t)__cvta_generic_to_shared(sAh);
    const uint32_t sAl_b = (uint32_t)__cvta_generic_to_shared(sAl);
    const uint32_t sB_b  = (uint32_t)__cvta_generic_to_shared(sB);

    // ldmatrix lane coords (within 16x16 block):
    const int matq = lane >> 3;
    const int lrow = lane & 7;
    const int a_r = lrow + ((matq & 1) << 3);
    const int a_c = (matq >> 1) << 3;
    const int b_r = lrow + ((matq >> 1) << 3);
    const int b_c = (matq & 1) << 3;

    float acc[4][4][4];
    #pragma unroll
    for (int i = 0; i < 4; ++i)
        #pragma unroll
        for (int j = 0; j < 4; ++j)
            #pragma unroll
            for (int k = 0; k < 4; ++k) acc[i][j][k] = 0.0f;

    for (int k0 = 0; k0 < H_; k0 += BK) {
        __syncthreads();   // previous iteration's math done before overwrite
        #pragma unroll
        for (int i = tid; i < 512; i += 256) {
            const int r = i >> 2;
            const int c = (i & 3) << 3;     // fp16 col, 8 per uint4
            const size_t ga = (size_t)(m0 + r) * H_ + k0 + c;
            const size_t gb = (size_t)(n0 + r) * H_ + k0 + c;
            *(uint4*)&sAh[r * PITCH + c] = *(const uint4*)&g_a_hi[ga];
            *(uint4*)&sAl[r * PITCH + c] = *(const uint4*)&g_a_lo[ga];
            *(uint4*)&sB [r * PITCH + c] = *(const uint4*)&g_bt[gb];
        }
        __syncthreads();

        #pragma unroll
        for (int ks = 0; ks < 2; ++ks) {
            const int ko = ks * 16;
            uint32_t ah[4][4], bf[4][2];
            #pragma unroll
            for (int mf = 0; mf < 4; ++mf) {
                const int r = wm + mf * 16 + a_r;
                ldsm_x4(ah[mf], sAh_b + (uint32_t)(r * PITCH + ko + a_c) * 2);
            }
            #pragma unroll
            for (int np = 0; np < 2; ++np) {
                const int r = wn + np * 16 + b_r;
                uint32_t q[4];
                ldsm_x4(q, sB_b + (uint32_t)(r * PITCH + ko + b_c) * 2);
                bf[np * 2][0] = q[0]; bf[np * 2][1] = q[1];
                bf[np * 2 + 1][0] = q[2]; bf[np * 2 + 1][1] = q[3];
            }
            #pragma unroll
            for (int mf = 0; mf < 4; ++mf)
                #pragma unroll
                for (int nf = 0; nf < 4; ++nf)
                    mma_f16(acc[mf][nf], ah[mf], bf[nf]);
            uint32_t al[4][4];
            #pragma unroll
            for (int mf = 0; mf < 4; ++mf) {
                const int r = wm + mf * 16 + a_r;
                ldsm_x4(al[mf], sAl_b + (uint32_t)(r * PITCH + ko + a_c) * 2);
            }
            #pragma unroll
            for (int mf = 0; mf < 4; ++mf)
                #pragma unroll
                for (int nf = 0; nf < 4; ++nf)
                    mma_f16(acc[mf][nf], al[mf], bf[nf]);
        }
    }

    // Epilogue: direct gmem stores with bias.
    const int cr = lane >> 2;
    const int cc = (lane & 3) * 2;
    #pragma unroll
    for (int mf = 0; mf < 4; ++mf) {
        #pragma unroll
        for (int nf = 0; nf < 4; ++nf) {
            const int gr0 = m0 + wm + mf * 16 + cr;
            const int gc  = n0 + wn + nf * 8 + cc;
            const float b0 = bias[gc], b1 = bias[gc + 1];
            float2 v0 = make_float2(acc[mf][nf][0] + b0, acc[mf][nf][1] + b1);
            float2 v1 = make_float2(acc[mf][nf][2] + b0, acc[mf][nf][3] + b1);
            *(float2*)&C[(size_t)gr0 * D_ + gc]       = v0;
            *(float2*)&C[(size_t)(gr0 + 8) * D_ + gc] = v1;
        }
    }
}

// ---------------------------------------------------------------------------
// Launch. Inputs (metadata order):
//   d_in[0] embeddings f32 [B,S,H]; d_in[1] proj_w f32 [H,D]; d_in[2] proj_b f32 [D]
//   d_in[3] masks i32 [B,S]; d_in[4] word_ids i32 [B,S]
// d_out: [ out (M_*D_ f32) | token_masks (M_ f32 0/1) ]
// ---------------------------------------------------------------------------
extern "C" void kernel_launch(void* const* d_in, const int* in_sizes, int n_in,
                              void* d_out, int out_size)
{
    const float* emb    = (const float*)d_in[0];
    const float* proj_w = (const float*)d_in[1];
    const float* proj_b = (const float*)d_in[2];
    const int*   masks  = (const int*)d_in[3];
    const int*   wids   = (const int*)d_in[4];

    float* out_proj  = (float*)d_out;
    float* out_masks = (float*)d_out + (size_t)M_ * D_;

    zero_bounds_kernel<<<M_ / 256, 256>>>();
    calc_bounds_kernel<<<(B_ * S_) / 256, 256>>>(wids);

    dim3 g1(W_, B_);
    seg_mean_kernel<<<g1, 192>>>(emb, masks, out_masks);

    dim3 gw(D_ / 32, H_ / 32);
    wsplit_kernel<<<gw, dim3(32, 8)>>>(proj_w);

    dim3 g2(D_ / 128, M_ / 128);   // (8, 128)
    gemm_mma_kernel<<<g2, 256>>>(proj_b, out_proj);
}